// round 12
// baseline (speedup 1.0000x reference)
#include <cuda_runtime.h>
#include <math.h>

#define BATCH 16
#define TQ 512
#define TK 1024
#define DIM 512

#define BM 128
#define BN 128
#define BK 16
#define PAD 4
#define LDA_S (BM + PAD)
#define LDB_S (BN + PAD)

// Scratch for projected queries (allocations are forbidden; __device__ array is the sanctioned path)
__device__ float g_aq[(long)BATCH * TQ * DIM];

// MODE 0: epilogue adds bias aux[col]   (Q projection)
// MODE 1: epilogue multiplies by aux[0] (score scale)
// MODE 2: plain
// TRANS_B 0: B is [N,K] (NT gemm, reduce over contiguous K of both operands)
// TRANS_B 1: B is [K,N] (NN gemm)
template <int TRANS_B, int MODE>
__global__ __launch_bounds__(256) void gemm_kernel(
    const float* __restrict__ A, const float* __restrict__ Bm, float* __restrict__ C,
    int M, int N, int K, int lda, int ldb, int ldc,
    long sA, long sB, long sC, const float* __restrict__ aux)
{
    __shared__ float As[BK][LDA_S];
    __shared__ float Bs[BK][LDB_S];

    const int b = blockIdx.z;
    A += (long)b * sA;
    Bm += (long)b * sB;
    C += (long)b * sC;

    const int row0 = blockIdx.y * BM;
    const int col0 = blockIdx.x * BN;
    const int tid = threadIdx.x;
    const int tx = tid & 15;   // 0..15 -> 8 cols each
    const int ty = tid >> 4;   // 0..15 -> 8 rows each

    float acc[8][8] = {};

    for (int k0 = 0; k0 < K; k0 += BK) {
        // ---- load A tile (BM x BK), A is [M,K] row-major ----
#pragma unroll
        for (int i = 0; i < 2; i++) {
            int f = tid + i * 256;         // 0..511 float4 slots
            int r = f >> 2;                // 0..127
            int kq = (f & 3) * 4;          // 0,4,8,12
            float4 v = *(const float4*)&A[(long)(row0 + r) * lda + k0 + kq];
            As[kq + 0][r] = v.x;
            As[kq + 1][r] = v.y;
            As[kq + 2][r] = v.z;
            As[kq + 3][r] = v.w;
        }
        // ---- load B tile ----
        if (TRANS_B == 0) {
            // B is [N,K]
#pragma unroll
            for (int i = 0; i < 2; i++) {
                int f = tid + i * 256;
                int r = f >> 2;
                int kq = (f & 3) * 4;
                float4 v = *(const float4*)&Bm[(long)(col0 + r) * ldb + k0 + kq];
                Bs[kq + 0][r] = v.x;
                Bs[kq + 1][r] = v.y;
                Bs[kq + 2][r] = v.z;
                Bs[kq + 3][r] = v.w;
            }
        } else {
            // B is [K,N]
#pragma unroll
            for (int i = 0; i < 2; i++) {
                int f = tid + i * 256;
                int kr = f >> 5;           // 0..15
                int c = (f & 31) * 4;      // 0..124
                float4 v = *(const float4*)&Bm[(long)(k0 + kr) * ldb + col0 + c];
                *(float4*)&Bs[kr][c] = v;
            }
        }
        __syncthreads();

#pragma unroll
        for (int kk = 0; kk < BK; kk++) {
            float a[8], bb[8];
            *(float4*)&a[0]  = *(const float4*)&As[kk][ty * 8];
            *(float4*)&a[4]  = *(const float4*)&As[kk][ty * 8 + 4];
            *(float4*)&bb[0] = *(const float4*)&Bs[kk][tx * 8];
            *(float4*)&bb[4] = *(const float4*)&Bs[kk][tx * 8 + 4];
#pragma unroll
            for (int i = 0; i < 8; i++)
#pragma unroll
                for (int j = 0; j < 8; j++)
                    acc[i][j] += a[i] * bb[j];
        }
        __syncthreads();
    }

    float s = 1.0f;
    if (MODE == 1) s = aux[0];

#pragma unroll
    for (int i = 0; i < 8; i++) {
        int r = row0 + ty * 8 + i;
#pragma unroll
        for (int j = 0; j < 8; j += 4) {
            int c = col0 + tx * 8 + j;
            float4 v;
            v.x = acc[i][j + 0];
            v.y = acc[i][j + 1];
            v.z = acc[i][j + 2];
            v.w = acc[i][j + 3];
            if (MODE == 0) {
                v.x += aux[c + 0];
                v.y += aux[c + 1];
                v.z += aux[c + 2];
                v.w += aux[c + 3];
            }
            if (MODE == 1) {
                v.x *= s; v.y *= s; v.z *= s; v.w *= s;
            }
            *(float4*)&C[(long)r * ldc + c] = v;
        }
    }
}

// In-place masked softmax over rows of length TK. One block (256 threads) per row.
__global__ __launch_bounds__(256) void softmax_kernel(
    float* __restrict__ attn, const int* __restrict__ lens)
{
    const int row = blockIdx.x;          // b*TQ + q
    const int b = row / TQ;
    const int len = lens[b];
    float* p = attn + (long)row * TK;
    const int tid = threadIdx.x;

    __shared__ float red[8];

    float vals[4];
    float m = -INFINITY;
#pragma unroll
    for (int i = 0; i < 4; i++) {
        int k = tid + i * 256;
        vals[i] = (k < len) ? p[k] : -INFINITY;
        m = fmaxf(m, vals[i]);
    }
    // block max
#pragma unroll
    for (int o = 16; o > 0; o >>= 1)
        m = fmaxf(m, __shfl_xor_sync(0xffffffffu, m, o));
    if ((tid & 31) == 0) red[tid >> 5] = m;
    __syncthreads();
    if (tid < 32) {
        float t = (tid < 8) ? red[tid] : -INFINITY;
#pragma unroll
        for (int o = 4; o > 0; o >>= 1)
            t = fmaxf(t, __shfl_xor_sync(0xffffffffu, t, o));
        if (tid == 0) red[0] = t;
    }
    __syncthreads();
    m = red[0];
    __syncthreads();

    float sum = 0.0f;
#pragma unroll
    for (int i = 0; i < 4; i++) {
        int k = tid + i * 256;
        float e = (k < len) ? __expf(vals[i] - m) : 0.0f;
        vals[i] = e;
        sum += e;
    }
    // block sum
#pragma unroll
    for (int o = 16; o > 0; o >>= 1)
        sum += __shfl_xor_sync(0xffffffffu, sum, o);
    if ((tid & 31) == 0) red[tid >> 5] = sum;
    __syncthreads();
    if (tid < 32) {
        float t = (tid < 8) ? red[tid] : 0.0f;
#pragma unroll
        for (int o = 4; o > 0; o >>= 1)
            t += __shfl_xor_sync(0xffffffffu, t, o);
        if (tid == 0) red[0] = t;
    }
    __syncthreads();
    const float inv = 1.0f / red[0];

#pragma unroll
    for (int i = 0; i < 4; i++) {
        int k = tid + i * 256;
        p[k] = vals[i] * inv;
    }
}

extern "C" void kernel_launch(void* const* d_in, const int* in_sizes, int n_in,
                              void* d_out, int out_size) {
    (void)in_sizes; (void)n_in; (void)out_size;
    const float* query = (const float*)d_in[0];  // [B, TQ, D]
    const float* keys  = (const float*)d_in[1];  // [B, TK, D]
    const int*   lens  = (const int*)d_in[2];    // [B]
    const float* Wq    = (const float*)d_in[3];  // [D, D]
    const float* bq    = (const float*)d_in[4];  // [D]
    const float* scale = (const float*)d_in[5];  // [1]

    float* out = (float*)d_out;
    float* context = out;                              // [B, TQ, D]
    float* attn = out + (long)BATCH * TQ * DIM;        // [B, TQ, TK]

    float* aq = nullptr;
    cudaGetSymbolAddress((void**)&aq, g_aq);

    // 1) AQ = Q @ Wq^T + bq   (NT, bias epilogue)
    {
        dim3 grid(DIM / BN, TQ / BM, BATCH);
        gemm_kernel<0, 0><<<grid, 256>>>(
            query, Wq, aq,
            TQ, DIM, DIM, DIM, DIM, DIM,
            (long)TQ * DIM, 0L, (long)TQ * DIM, bq);
    }
    // 2) S = AQ @ K^T * scale  (NT, scale epilogue) -> attn region (pre-softmax)
    {
        dim3 grid(TK / BN, TQ / BM, BATCH);
        gemm_kernel<0, 1><<<grid, 256>>>(
            aq, keys, attn,
            TQ, TK, DIM, DIM, DIM, TK,
            (long)TQ * DIM, (long)TK * DIM, (long)TQ * TK, scale);
    }
    // 3) masked softmax in place over TK
    softmax_kernel<<<BATCH * TQ, 256>>>(attn, lens);

    // 4) context = attn @ K   (NN, plain)
    {
        dim3 grid(DIM / BN, TQ / BM, BATCH);
        gemm_kernel<1, 2><<<grid, 256>>>(
            attn, keys, context,
            TQ, DIM, TK, TK, DIM, DIM,
            (long)TQ * TK, (long)TK * DIM, (long)TQ * DIM, nullptr);
    }
}

// round 13
// speedup vs baseline: 1.0018x; 1.0018x over previous
#include <cuda_runtime.h>
#include <math.h>

#define BATCH 16
#define TQ 512
#define TK 1024
#define DIM 512

#define BM 128
#define BN 128
#define BK 16
#define PAD 4
#define LDA_S (BM + PAD)
#define LDB_S (BN + PAD)

// Scratch for projected queries (allocations are forbidden; __device__ array is the sanctioned path)
__device__ float g_aq[(long)BATCH * TQ * DIM];

// MODE 0: epilogue adds bias aux[col]   (Q projection)
// MODE 1: epilogue multiplies by aux[0] (score scale)
// MODE 2: plain
// TRANS_B 0: B is [N,K] (NT gemm, reduce over contiguous K of both operands)
// TRANS_B 1: B is [K,N] (NN gemm)
template <int TRANS_B, int MODE>
__global__ __launch_bounds__(256) void gemm_kernel(
    const float* __restrict__ A, const float* __restrict__ Bm, float* __restrict__ C,
    int M, int N, int K, int lda, int ldb, int ldc,
    long sA, long sB, long sC, const float* __restrict__ aux)
{
    __shared__ float As[BK][LDA_S];
    __shared__ float Bs[BK][LDB_S];

    const int b = blockIdx.z;
    A += (long)b * sA;
    Bm += (long)b * sB;
    C += (long)b * sC;

    const int row0 = blockIdx.y * BM;
    const int col0 = blockIdx.x * BN;
    const int tid = threadIdx.x;
    const int tx = tid & 15;   // 0..15 -> 8 cols each
    const int ty = tid >> 4;   // 0..15 -> 8 rows each

    float acc[8][8] = {};

    for (int k0 = 0; k0 < K; k0 += BK) {
        // ---- load A tile (BM x BK), A is [M,K] row-major ----
#pragma unroll
        for (int i = 0; i < 2; i++) {
            int f = tid + i * 256;         // 0..511 float4 slots
            int r = f >> 2;                // 0..127
            int kq = (f & 3) * 4;          // 0,4,8,12
            float4 v = *(const float4*)&A[(long)(row0 + r) * lda + k0 + kq];
            As[kq + 0][r] = v.x;
            As[kq + 1][r] = v.y;
            As[kq + 2][r] = v.z;
            As[kq + 3][r] = v.w;
        }
        // ---- load B tile ----
        if (TRANS_B == 0) {
            // B is [N,K]
#pragma unroll
            for (int i = 0; i < 2; i++) {
                int f = tid + i * 256;
                int r = f >> 2;
                int kq = (f & 3) * 4;
                float4 v = *(const float4*)&Bm[(long)(col0 + r) * ldb + k0 + kq];
                Bs[kq + 0][r] = v.x;
                Bs[kq + 1][r] = v.y;
                Bs[kq + 2][r] = v.z;
                Bs[kq + 3][r] = v.w;
            }
        } else {
            // B is [K,N]
#pragma unroll
            for (int i = 0; i < 2; i++) {
                int f = tid + i * 256;
                int kr = f >> 5;           // 0..15
                int c = (f & 31) * 4;      // 0..124
                float4 v = *(const float4*)&Bm[(long)(k0 + kr) * ldb + col0 + c];
                *(float4*)&Bs[kr][c] = v;
            }
        }
        __syncthreads();

#pragma unroll
        for (int kk = 0; kk < BK; kk++) {
            float a[8], bb[8];
            *(float4*)&a[0]  = *(const float4*)&As[kk][ty * 8];
            *(float4*)&a[4]  = *(const float4*)&As[kk][ty * 8 + 4];
            *(float4*)&bb[0] = *(const float4*)&Bs[kk][tx * 8];
            *(float4*)&bb[4] = *(const float4*)&Bs[kk][tx * 8 + 4];
#pragma unroll
            for (int i = 0; i < 8; i++)
#pragma unroll
                for (int j = 0; j < 8; j++)
                    acc[i][j] += a[i] * bb[j];
        }
        __syncthreads();
    }

    float s = 1.0f;
    if (MODE == 1) s = aux[0];

#pragma unroll
    for (int i = 0; i < 8; i++) {
        int r = row0 + ty * 8 + i;
#pragma unroll
        for (int j = 0; j < 8; j += 4) {
            int c = col0 + tx * 8 + j;
            float4 v;
            v.x = acc[i][j + 0];
            v.y = acc[i][j + 1];
            v.z = acc[i][j + 2];
            v.w = acc[i][j + 3];
            if (MODE == 0) {
                v.x += aux[c + 0];
                v.y += aux[c + 1];
                v.z += aux[c + 2];
                v.w += aux[c + 3];
            }
            if (MODE == 1) {
                v.x *= s; v.y *= s; v.z *= s; v.w *= s;
            }
            *(float4*)&C[(long)r * ldc + c] = v;
        }
    }
}

// In-place masked softmax over rows of length TK. One block (256 threads) per row.
__global__ __launch_bounds__(256) void softmax_kernel(
    float* __restrict__ attn, const int* __restrict__ lens)
{
    const int row = blockIdx.x;          // b*TQ + q
    const int b = row / TQ;
    const int len = lens[b];
    float* p = attn + (long)row * TK;
    const int tid = threadIdx.x;

    __shared__ float red[8];

    float vals[4];
    float m = -INFINITY;
#pragma unroll
    for (int i = 0; i < 4; i++) {
        int k = tid + i * 256;
        vals[i] = (k < len) ? p[k] : -INFINITY;
        m = fmaxf(m, vals[i]);
    }
    // block max
#pragma unroll
    for (int o = 16; o > 0; o >>= 1)
        m = fmaxf(m, __shfl_xor_sync(0xffffffffu, m, o));
    if ((tid & 31) == 0) red[tid >> 5] = m;
    __syncthreads();
    if (tid < 32) {
        float t = (tid < 8) ? red[tid] : -INFINITY;
#pragma unroll
        for (int o = 4; o > 0; o >>= 1)
            t = fmaxf(t, __shfl_xor_sync(0xffffffffu, t, o));
        if (tid == 0) red[0] = t;
    }
    __syncthreads();
    m = red[0];
    __syncthreads();

    float sum = 0.0f;
#pragma unroll
    for (int i = 0; i < 4; i++) {
        int k = tid + i * 256;
        float e = (k < len) ? __expf(vals[i] - m) : 0.0f;
        vals[i] = e;
        sum += e;
    }
    // block sum
#pragma unroll
    for (int o = 16; o > 0; o >>= 1)
        sum += __shfl_xor_sync(0xffffffffu, sum, o);
    if ((tid & 31) == 0) red[tid >> 5] = sum;
    __syncthreads();
    if (tid < 32) {
        float t = (tid < 8) ? red[tid] : 0.0f;
#pragma unroll
        for (int o = 4; o > 0; o >>= 1)
            t += __shfl_xor_sync(0xffffffffu, t, o);
        if (tid == 0) red[0] = t;
    }
    __syncthreads();
    const float inv = 1.0f / red[0];

#pragma unroll
    for (int i = 0; i < 4; i++) {
        int k = tid + i * 256;
        p[k] = vals[i] * inv;
    }
}

extern "C" void kernel_launch(void* const* d_in, const int* in_sizes, int n_in,
                              void* d_out, int out_size) {
    (void)in_sizes; (void)n_in; (void)out_size;
    const float* query = (const float*)d_in[0];  // [B, TQ, D]
    const float* keys  = (const float*)d_in[1];  // [B, TK, D]
    const int*   lens  = (const int*)d_in[2];    // [B]
    const float* Wq    = (const float*)d_in[3];  // [D, D]
    const float* bq    = (const float*)d_in[4];  // [D]
    const float* scale = (const float*)d_in[5];  // [1]

    float* out = (float*)d_out;
    float* context = out;                              // [B, TQ, D]
    float* attn = out + (long)BATCH * TQ * DIM;        // [B, TQ, TK]

    float* aq = nullptr;
    cudaGetSymbolAddress((void**)&aq, g_aq);

    // 1) AQ = Q @ Wq^T + bq   (NT, bias epilogue)
    {
        dim3 grid(DIM / BN, TQ / BM, BATCH);
        gemm_kernel<0, 0><<<grid, 256>>>(
            query, Wq, aq,
            TQ, DIM, DIM, DIM, DIM, DIM,
            (long)TQ * DIM, 0L, (long)TQ * DIM, bq);
    }
    // 2) S = AQ @ K^T * scale  (NT, scale epilogue) -> attn region (pre-softmax)
    {
        dim3 grid(TK / BN, TQ / BM, BATCH);
        gemm_kernel<0, 1><<<grid, 256>>>(
            aq, keys, attn,
            TQ, TK, DIM, DIM, DIM, TK,
            (long)TQ * DIM, (long)TK * DIM, (long)TQ * TK, scale);
    }
    // 3) masked softmax in place over TK
    softmax_kernel<<<BATCH * TQ, 256>>>(attn, lens);

    // 4) context = attn @ K   (NN, plain)
    {
        dim3 grid(DIM / BN, TQ / BM, BATCH);
        gemm_kernel<1, 2><<<grid, 256>>>(
            attn, keys, context,
            TQ, DIM, TK, TK, DIM, DIM,
            (long)TQ * TK, (long)TK * DIM, (long)TQ * DIM, nullptr);
    }
}

// round 14
// speedup vs baseline: 1.0036x; 1.0018x over previous
#include <cuda_runtime.h>
#include <math.h>

#define BATCH 16
#define TQ 512
#define TK 1024
#define DIM 512

#define BM 128
#define BN 128
#define BK 16
#define PAD 4
#define LDA_S (BM + PAD)
#define LDB_S (BN + PAD)

// Scratch for projected queries (allocations are forbidden; __device__ array is the sanctioned path)
__device__ float g_aq[(long)BATCH * TQ * DIM];

// MODE 0: epilogue adds bias aux[col]   (Q projection)
// MODE 1: epilogue multiplies by aux[0] (score scale)
// MODE 2: plain
// TRANS_B 0: B is [N,K] (NT gemm, reduce over contiguous K of both operands)
// TRANS_B 1: B is [K,N] (NN gemm)
template <int TRANS_B, int MODE>
__global__ __launch_bounds__(256) void gemm_kernel(
    const float* __restrict__ A, const float* __restrict__ Bm, float* __restrict__ C,
    int M, int N, int K, int lda, int ldb, int ldc,
    long sA, long sB, long sC, const float* __restrict__ aux)
{
    __shared__ float As[BK][LDA_S];
    __shared__ float Bs[BK][LDB_S];

    const int b = blockIdx.z;
    A += (long)b * sA;
    Bm += (long)b * sB;
    C += (long)b * sC;

    const int row0 = blockIdx.y * BM;
    const int col0 = blockIdx.x * BN;
    const int tid = threadIdx.x;
    const int tx = tid & 15;   // 0..15 -> 8 cols each
    const int ty = tid >> 4;   // 0..15 -> 8 rows each

    float acc[8][8] = {};

    for (int k0 = 0; k0 < K; k0 += BK) {
        // ---- load A tile (BM x BK), A is [M,K] row-major ----
#pragma unroll
        for (int i = 0; i < 2; i++) {
            int f = tid + i * 256;         // 0..511 float4 slots
            int r = f >> 2;                // 0..127
            int kq = (f & 3) * 4;          // 0,4,8,12
            float4 v = *(const float4*)&A[(long)(row0 + r) * lda + k0 + kq];
            As[kq + 0][r] = v.x;
            As[kq + 1][r] = v.y;
            As[kq + 2][r] = v.z;
            As[kq + 3][r] = v.w;
        }
        // ---- load B tile ----
        if (TRANS_B == 0) {
            // B is [N,K]
#pragma unroll
            for (int i = 0; i < 2; i++) {
                int f = tid + i * 256;
                int r = f >> 2;
                int kq = (f & 3) * 4;
                float4 v = *(const float4*)&Bm[(long)(col0 + r) * ldb + k0 + kq];
                Bs[kq + 0][r] = v.x;
                Bs[kq + 1][r] = v.y;
                Bs[kq + 2][r] = v.z;
                Bs[kq + 3][r] = v.w;
            }
        } else {
            // B is [K,N]
#pragma unroll
            for (int i = 0; i < 2; i++) {
                int f = tid + i * 256;
                int kr = f >> 5;           // 0..15
                int c = (f & 31) * 4;      // 0..124
                float4 v = *(const float4*)&Bm[(long)(k0 + kr) * ldb + col0 + c];
                *(float4*)&Bs[kr][c] = v;
            }
        }
        __syncthreads();

#pragma unroll
        for (int kk = 0; kk < BK; kk++) {
            float a[8], bb[8];
            *(float4*)&a[0]  = *(const float4*)&As[kk][ty * 8];
            *(float4*)&a[4]  = *(const float4*)&As[kk][ty * 8 + 4];
            *(float4*)&bb[0] = *(const float4*)&Bs[kk][tx * 8];
            *(float4*)&bb[4] = *(const float4*)&Bs[kk][tx * 8 + 4];
#pragma unroll
            for (int i = 0; i < 8; i++)
#pragma unroll
                for (int j = 0; j < 8; j++)
                    acc[i][j] += a[i] * bb[j];
        }
        __syncthreads();
    }

    float s = 1.0f;
    if (MODE == 1) s = aux[0];

#pragma unroll
    for (int i = 0; i < 8; i++) {
        int r = row0 + ty * 8 + i;
#pragma unroll
        for (int j = 0; j < 8; j += 4) {
            int c = col0 + tx * 8 + j;
            float4 v;
            v.x = acc[i][j + 0];
            v.y = acc[i][j + 1];
            v.z = acc[i][j + 2];
            v.w = acc[i][j + 3];
            if (MODE == 0) {
                v.x += aux[c + 0];
                v.y += aux[c + 1];
                v.z += aux[c + 2];
                v.w += aux[c + 3];
            }
            if (MODE == 1) {
                v.x *= s; v.y *= s; v.z *= s; v.w *= s;
            }
            *(float4*)&C[(long)r * ldc + c] = v;
        }
    }
}

// In-place masked softmax over rows of length TK. One block (256 threads) per row.
__global__ __launch_bounds__(256) void softmax_kernel(
    float* __restrict__ attn, const int* __restrict__ lens)
{
    const int row = blockIdx.x;          // b*TQ + q
    const int b = row / TQ;
    const int len = lens[b];
    float* p = attn + (long)row * TK;
    const int tid = threadIdx.x;

    __shared__ float red[8];

    float vals[4];
    float m = -INFINITY;
#pragma unroll
    for (int i = 0; i < 4; i++) {
        int k = tid + i * 256;
        vals[i] = (k < len) ? p[k] : -INFINITY;
        m = fmaxf(m, vals[i]);
    }
    // block max
#pragma unroll
    for (int o = 16; o > 0; o >>= 1)
        m = fmaxf(m, __shfl_xor_sync(0xffffffffu, m, o));
    if ((tid & 31) == 0) red[tid >> 5] = m;
    __syncthreads();
    if (tid < 32) {
        float t = (tid < 8) ? red[tid] : -INFINITY;
#pragma unroll
        for (int o = 4; o > 0; o >>= 1)
            t = fmaxf(t, __shfl_xor_sync(0xffffffffu, t, o));
        if (tid == 0) red[0] = t;
    }
    __syncthreads();
    m = red[0];
    __syncthreads();

    float sum = 0.0f;
#pragma unroll
    for (int i = 0; i < 4; i++) {
        int k = tid + i * 256;
        float e = (k < len) ? __expf(vals[i] - m) : 0.0f;
        vals[i] = e;
        sum += e;
    }
    // block sum
#pragma unroll
    for (int o = 16; o > 0; o >>= 1)
        sum += __shfl_xor_sync(0xffffffffu, sum, o);
    if ((tid & 31) == 0) red[tid >> 5] = sum;
    __syncthreads();
    if (tid < 32) {
        float t = (tid < 8) ? red[tid] : 0.0f;
#pragma unroll
        for (int o = 4; o > 0; o >>= 1)
            t += __shfl_xor_sync(0xffffffffu, t, o);
        if (tid == 0) red[0] = t;
    }
    __syncthreads();
    const float inv = 1.0f / red[0];

#pragma unroll
    for (int i = 0; i < 4; i++) {
        int k = tid + i * 256;
        p[k] = vals[i] * inv;
    }
}

extern "C" void kernel_launch(void* const* d_in, const int* in_sizes, int n_in,
                              void* d_out, int out_size) {
    (void)in_sizes; (void)n_in; (void)out_size;
    const float* query = (const float*)d_in[0];  // [B, TQ, D]
    const float* keys  = (const float*)d_in[1];  // [B, TK, D]
    const int*   lens  = (const int*)d_in[2];    // [B]
    const float* Wq    = (const float*)d_in[3];  // [D, D]
    const float* bq    = (const float*)d_in[4];  // [D]
    const float* scale = (const float*)d_in[5];  // [1]

    float* out = (float*)d_out;
    float* context = out;                              // [B, TQ, D]
    float* attn = out + (long)BATCH * TQ * DIM;        // [B, TQ, TK]

    float* aq = nullptr;
    cudaGetSymbolAddress((void**)&aq, g_aq);

    // 1) AQ = Q @ Wq^T + bq   (NT, bias epilogue)
    {
        dim3 grid(DIM / BN, TQ / BM, BATCH);
        gemm_kernel<0, 0><<<grid, 256>>>(
            query, Wq, aq,
            TQ, DIM, DIM, DIM, DIM, DIM,
            (long)TQ * DIM, 0L, (long)TQ * DIM, bq);
    }
    // 2) S = AQ @ K^T * scale  (NT, scale epilogue) -> attn region (pre-softmax)
    {
        dim3 grid(TK / BN, TQ / BM, BATCH);
        gemm_kernel<0, 1><<<grid, 256>>>(
            aq, keys, attn,
            TQ, TK, DIM, DIM, DIM, TK,
            (long)TQ * DIM, (long)TK * DIM, (long)TQ * TK, scale);
    }
    // 3) masked softmax in place over TK
    softmax_kernel<<<BATCH * TQ, 256>>>(attn, lens);

    // 4) context = attn @ K   (NN, plain)
    {
        dim3 grid(DIM / BN, TQ / BM, BATCH);
        gemm_kernel<1, 2><<<grid, 256>>>(
            attn, keys, context,
            TQ, DIM, TK, TK, DIM, DIM,
            (long)TQ * TK, (long)TK * DIM, (long)TQ * DIM, nullptr);
    }
}